// round 14
// baseline (speedup 1.0000x reference)
#include <cuda_runtime.h>
#include <cuda.h>
#include <math.h>

#define XS 540
#define YS 540
#define BATCH 4
#define NBOX 64
#define TILE 32
#define TXN 17
#define TYN 17
#define NBLOCKS (TXN*TYN*BATCH)
#define NTICKETS (NBLOCKS*8)
#define FIXSCALE 67108864.0   // 2^26

__device__ unsigned long long g_acc[BATCH][2];
__device__ unsigned int g_done;

struct BoxC { float cx, cy, c, s, hw, hl, hv; };

// ---------------- device helpers ----------------
__device__ __forceinline__ unsigned int smem_u32(const void* p) {
    return (unsigned int)__cvta_generic_to_shared(p);
}
__device__ __forceinline__ void mbar_init(unsigned int a, unsigned int cnt) {
    asm volatile("mbarrier.init.shared.b64 [%0], %1;" :: "r"(a), "r"(cnt) : "memory");
}
__device__ __forceinline__ void mbar_expect_tx(unsigned int a, unsigned int bytes) {
    asm volatile("mbarrier.arrive.expect_tx.shared.b64 _, [%0], %1;" :: "r"(a), "r"(bytes) : "memory");
}
__device__ __forceinline__ void mbar_wait(unsigned int a, unsigned int parity) {
    unsigned int done;
    asm volatile(
        "{\n\t.reg .pred p;\n\t"
        "mbarrier.try_wait.parity.acquire.cta.shared::cta.b64 p, [%1], %2;\n\t"
        "selp.b32 %0, 1, 0, p;\n\t}"
        : "=r"(done) : "r"(a), "r"(parity) : "memory");
    if (!done) {
        asm volatile(
            "{\n\t.reg .pred P1;\n\t"
            "WL_%=:\n\t"
            "mbarrier.try_wait.parity.acquire.cta.shared::cta.b64 P1, [%0], %1, 0x989680;\n\t"
            "@P1 bra.uni WD_%=;\n\t"
            "bra.uni WL_%=;\n\t"
            "WD_%=:\n\t}"
            :: "r"(a), "r"(parity) : "memory");
    }
}
__device__ __forceinline__ void tma_load_2d(unsigned int smem_dst, const CUtensorMap* tm,
                                            int cx, int cy, unsigned int mbar) {
    asm volatile(
        "cp.async.bulk.tensor.2d.shared::cta.global.tile.mbarrier::complete_tx::bytes "
        "[%0], [%1, {%2, %3}], [%4];"
        :: "r"(smem_dst), "l"(tm), "r"(cx), "r"(cy), "r"(mbar) : "memory");
}

__device__ __forceinline__ void box_prologue(const float* boxes, int b, int tid, int lane, int wrp,
                                             BoxC* bc, unsigned int* sm_mask) {
    if (tid < NBOX) {
        const float* p = boxes + (b * NBOX + tid) * 7;
        const float p0 = p[0], p1 = p[1], p3 = p[3], p4 = p[4], p5 = p[5], p6 = p[6];
        BoxC v;
        v.cx = (p0 + 54.0f) * 5.0f;
        v.cy = (p1 + 54.0f) * 5.0f;
        v.hw = p3 * 2.5f;
        v.hl = p4 * 2.5f;
        float sn, cn;
        __sincosf(p6, &sn, &cn);
        v.c  = cn;
        v.s  = -sn;
        v.hv = p5 * 0.2f;
        bc[tid] = v;

        const float ex = fabsf(v.c) * v.hw + fabsf(v.s) * v.hl;
        const float ey = fabsf(v.s) * v.hw + fabsf(v.c) * v.hl;
        const float tx0 = (float)(blockIdx.x * TILE);
        const float ty0 = (float)(blockIdx.y * TILE);
        const bool hit = (v.cx - ex <= tx0 + (float)(TILE - 1)) && (v.cx + ex >= tx0) &&
                         (v.cy - ey <= ty0 + (float)(TILE - 1)) && (v.cy + ey >= ty0);
        const unsigned int m = __ballot_sync(0xffffffffu, hit);
        if (lane == 0) sm_mask[wrp] = m;
    }
}

__device__ __forceinline__ void raster4(unsigned int m0, unsigned int m1, const BoxC* bc,
                                        float fx0, float fy, float gt[4]) {
    #pragma unroll
    for (int half = 0; half < 2; half++) {
        unsigned int mm = half ? m1 : m0;
        const int base = half ? 32 : 0;
        while (mm) {
            const int i = __ffs(mm) - 1;
            mm &= mm - 1u;
            const BoxC v = bc[base + i];
            const float dx = fx0 - v.cx;
            const float dy = fy - v.cy;
            float lx = dx * v.c - dy * v.s;
            float ly = dx * v.s + dy * v.c;
            #pragma unroll
            for (int j = 0; j < 4; j++) {
                const bool inside = (fabsf(lx) <= v.hw) && (fabsf(ly) <= v.hl);
                gt[j] = inside ? v.hv : gt[j];
                lx += v.c;
                ly += v.s;
            }
        }
    }
}

template <bool CHECK>
__device__ __forceinline__ void loss4(bool ok, const float gt[4], const float* xvp, const float* hhp,
                                      float& sc0, float& sc1, int& cv) {
    #pragma unroll
    for (int j = 0; j < 4; j++) {
        const float g  = gt[j];
        const bool pos = (g > 0.0f);
        bool valid = pos || (hhp[j] > 0.0f);
        if (CHECK) valid = valid && ok;
        const float xl = xvp[j];

        const float weight = pos ? 5.0f : 0.1f;
        const float e  = __expf(-fabsf(xl));
        const float d  = 1.0f + e;
        const float bce = fmaxf(xl, 0.0f) - xl * g + __logf(d);
        const float rd = __fdividef(1.0f, d);
        const float p  = (xl >= 0.0f) ? rd : e * rd;
        const float u  = fmaf(p, 1.0f - 2.0f * g, g);
        const float aw = 0.75f - 0.5f * g;
        const float contrib = weight * bce * fmaf(u * u, aw, 1.0f);
        if (j & 1) sc1 += valid ? contrib : 0.0f;
        else       sc0 += valid ? contrib : 0.0f;
        cv += valid ? 1 : 0;
    }
}

// warp-level finish: no barriers, no smem staging
__device__ __forceinline__ void finish_warp(int b, int lane, float sc, int cv, float* out) {
    const int cnt = __reduce_add_sync(0xffffffffu, cv);
    #pragma unroll
    for (int st = 16; st > 0; st >>= 1)
        sc += __shfl_xor_sync(0xffffffffu, sc, st);

    if (lane == 0) {
        atomicAdd(&g_acc[b][0], (unsigned long long)cnt);
        atomicAdd(&g_acc[b][1], (unsigned long long)llrint((double)sc * FIXSCALE));
        __threadfence();
        const unsigned int ticket = atomicAdd(&g_done, 1u);
        if (ticket == NTICKETS - 1) {
            float total = 0.0f, ns = 0.0f;
            #pragma unroll
            for (int bb = 0; bb < BATCH; bb++) {
                const double cnt_b = (double)g_acc[bb][0];
                if (cnt_b > 0.0) {
                    const double s = (double)g_acc[bb][1] / FIXSCALE;
                    total += (float)(0.5 * s / fmax(cnt_b, 1.0));
                    ns += 1.0f;
                }
            }
            out[0] = (ns > 0.0f) ? (total / fmaxf(ns, 1.0f)) : total;
            #pragma unroll
            for (int bb = 0; bb < BATCH; bb++) {
                g_acc[bb][0] = 0ull; g_acc[bb][1] = 0ull;
            }
            __threadfence();
            g_done = 0u;
        }
    }
}

// ---------------- TMA kernel ----------------
__global__ void __launch_bounds__(256)
hm_loss_tma_kernel(const __grid_constant__ CUtensorMap tml,
                   const __grid_constant__ CUtensorMap tmh,
                   const float* __restrict__ boxes,
                   float* __restrict__ out)
{
    __shared__ __align__(1024) float sL[TILE * TILE];
    __shared__ __align__(1024) float sH[TILE * TILE];
    __shared__ __align__(8) unsigned long long mbar;
    __shared__ BoxC bc[NBOX];
    __shared__ unsigned int sm_mask[2];

    const int b    = blockIdx.z;
    const int tid  = threadIdx.x;
    const int lane = tid & 31;
    const int wrp  = tid >> 5;

    if (tid == 0) {
        const unsigned int mb = smem_u32(&mbar);
        mbar_init(mb, 1);
        asm volatile("fence.proxy.async.shared::cta;" ::: "memory");
        mbar_expect_tx(mb, 2 * TILE * TILE * 4);
        const int cx = blockIdx.x * TILE;
        const int cy = b * YS + blockIdx.y * TILE;
        tma_load_2d(smem_u32(sL), &tml, cx, cy, mb);
        tma_load_2d(smem_u32(sH), &tmh, cx, cy, mb);
    }

    box_prologue(boxes, b, tid, lane, wrp, bc, sm_mask);
    __syncthreads();

    const unsigned int m0 = sm_mask[0];
    const unsigned int m1 = sm_mask[1];

    const int x4 = blockIdx.x * TILE + (lane & 7) * 4;
    const int y  = blockIdx.y * TILE + (tid >> 3);

    float gt[4] = {0.f, 0.f, 0.f, 0.f};
    raster4(m0, m1, bc, (float)x4, (float)y, gt);

    mbar_wait(smem_u32(&mbar), 0);

    const int row = tid >> 3;
    unsigned int byte_off = (unsigned int)(row * 128 + (tid & 7) * 16);
    byte_off ^= ((byte_off >> 3) & 0x70u);   // SW128
    const float4 xl4 = *reinterpret_cast<const float4*>(
        reinterpret_cast<const char*>(sL) + byte_off);
    const float4 hh4 = *reinterpret_cast<const float4*>(
        reinterpret_cast<const char*>(sH) + byte_off);

    float sc0 = 0.0f, sc1 = 0.0f;
    int cv = 0;
    if (blockIdx.x < TXN - 1 && blockIdx.y < TYN - 1) {
        // interior block: all pixels in-bounds
        loss4<false>(true, gt, &xl4.x, &hh4.x, sc0, sc1, cv);
    } else {
        const bool ok = (x4 + 3 < XS) && (y < YS);
        loss4<true>(ok, gt, &xl4.x, &hh4.x, sc0, sc1, cv);
    }

    finish_warp(b, lane, sc0 + sc1, cv, out);
}

// ---------------- fallback LDG kernel ----------------
__global__ void __launch_bounds__(256)
hm_loss_ldg_kernel(const float* __restrict__ logits,
                   const float* __restrict__ boxes,
                   const float* __restrict__ hm,
                   float* __restrict__ out)
{
    __shared__ BoxC bc[NBOX];
    __shared__ unsigned int sm_mask[2];

    const int b    = blockIdx.z;
    const int tid  = threadIdx.x;
    const int lane = tid & 31;
    const int wrp  = tid >> 5;

    const int x4 = blockIdx.x * TILE + (lane & 7) * 4;
    const int y  = blockIdx.y * TILE + (tid >> 3);
    const bool ok = (x4 + 3 < XS) && (y < YS);

    float4 xl4 = make_float4(0.f, 0.f, 0.f, 0.f);
    float4 hh4 = make_float4(0.f, 0.f, 0.f, 0.f);
    if (ok) {
        const int idx = (b * YS + y) * XS + x4;
        xl4 = *reinterpret_cast<const float4*>(logits + idx);
        hh4 = *reinterpret_cast<const float4*>(hm + idx);
    }

    box_prologue(boxes, b, tid, lane, wrp, bc, sm_mask);
    __syncthreads();

    float gt[4] = {0.f, 0.f, 0.f, 0.f};
    raster4(sm_mask[0], sm_mask[1], bc, (float)x4, (float)y, gt);

    float sc0 = 0.0f, sc1 = 0.0f;
    int cv = 0;
    loss4<true>(ok, gt, &xl4.x, &hh4.x, sc0, sc1, cv);

    finish_warp(b, lane, sc0 + sc1, cv, out);
}

// ---------------- host ----------------
typedef CUresult (*EncFn)(CUtensorMap*, CUtensorMapDataType, cuuint32_t, void*,
                          const cuuint64_t*, const cuuint64_t*, const cuuint32_t*,
                          const cuuint32_t*, CUtensorMapInterleave, CUtensorMapSwizzle,
                          CUtensorMapL2promotion, CUtensorMapFloatOOBfill);

static EncFn get_encoder() {
    static EncFn fn = nullptr;
    static bool tried = false;
    if (!tried) {
        tried = true;
        void* p = nullptr;
        cudaDriverEntryPointQueryResult qr;
        if (cudaGetDriverEntryPointByVersion("cuTensorMapEncodeTiled", &p, 12000,
                                             cudaEnableDefault, &qr) == cudaSuccess &&
            qr == cudaDriverEntryPointSuccess) {
            fn = (EncFn)p;
        }
    }
    return fn;
}

static bool make_tmap(CUtensorMap* tm, const float* base, EncFn enc) {
    cuuint64_t gdim[2]    = { (cuuint64_t)XS, (cuuint64_t)(BATCH * YS) };
    cuuint64_t gstride[1] = { (cuuint64_t)XS * sizeof(float) };
    cuuint32_t box[2]     = { TILE, TILE };
    cuuint32_t estr[2]    = { 1, 1 };
    CUresult r = enc(tm, CU_TENSOR_MAP_DATA_TYPE_FLOAT32, 2, (void*)base,
                     gdim, gstride, box, estr,
                     CU_TENSOR_MAP_INTERLEAVE_NONE, CU_TENSOR_MAP_SWIZZLE_128B,
                     CU_TENSOR_MAP_L2_PROMOTION_L2_128B,
                     CU_TENSOR_MAP_FLOAT_OOB_FILL_NONE);
    return r == CUDA_SUCCESS;
}

extern "C" void kernel_launch(void* const* d_in, const int* in_sizes, int n_in,
                              void* d_out, int out_size)
{
    const float* arrs[3] = { (const float*)d_in[0],
                             (const float*)d_in[1],
                             (const float*)d_in[2] };
    const float* logits = arrs[0];
    const float* boxes  = arrs[1];
    const float* hmap   = arrs[2];
    if (n_in >= 3) {
        int bi = -1;
        for (int i = 0; i < 3; i++)
            if (in_sizes[i] == BATCH * NBOX * 7) { bi = i; break; }
        if (bi >= 0) {
            boxes = arrs[bi];
            int o0 = -1, o1 = -1;
            for (int i = 0; i < 3; i++) {
                if (i == bi) continue;
                if (o0 < 0) o0 = i; else o1 = i;
            }
            logits = arrs[o0];
            hmap   = arrs[o1];
        }
    }

    dim3 block(256, 1, 1);
    dim3 grid(TXN, TYN, BATCH);

    EncFn enc = get_encoder();
    CUtensorMap tml, tmh;
    bool tma_ok = false;
    if (enc) {
        tma_ok = make_tmap(&tml, logits, enc) && make_tmap(&tmh, hmap, enc);
    }

    if (tma_ok) {
        hm_loss_tma_kernel<<<grid, block>>>(tml, tmh, boxes, (float*)d_out);
    } else {
        hm_loss_ldg_kernel<<<grid, block>>>(logits, boxes, hmap, (float*)d_out);
    }
}

// round 15
// speedup vs baseline: 1.9875x; 1.9875x over previous
#include <cuda_runtime.h>
#include <cuda.h>
#include <math.h>

#define XS 540
#define YS 540
#define BATCH 4
#define NBOX 64
#define TILE 32
#define TXN 17
#define TYN 17
#define NBLOCKS (TXN*TYN*BATCH)
#define FIXSCALE 67108864.0   // 2^26

__device__ unsigned long long g_acc[BATCH][2];
__device__ unsigned int g_done;

struct BoxC { float cx, cy, c, s, hw, hl, hv; };

// ---------------- device helpers ----------------
__device__ __forceinline__ unsigned int smem_u32(const void* p) {
    return (unsigned int)__cvta_generic_to_shared(p);
}
__device__ __forceinline__ void mbar_init(unsigned int a, unsigned int cnt) {
    asm volatile("mbarrier.init.shared.b64 [%0], %1;" :: "r"(a), "r"(cnt) : "memory");
}
__device__ __forceinline__ void mbar_expect_tx(unsigned int a, unsigned int bytes) {
    asm volatile("mbarrier.arrive.expect_tx.shared.b64 _, [%0], %1;" :: "r"(a), "r"(bytes) : "memory");
}
__device__ __forceinline__ void mbar_wait(unsigned int a, unsigned int parity) {
    unsigned int done;
    asm volatile(
        "{\n\t.reg .pred p;\n\t"
        "mbarrier.try_wait.parity.acquire.cta.shared::cta.b64 p, [%1], %2;\n\t"
        "selp.b32 %0, 1, 0, p;\n\t}"
        : "=r"(done) : "r"(a), "r"(parity) : "memory");
    if (!done) {
        asm volatile(
            "{\n\t.reg .pred P1;\n\t"
            "WL_%=:\n\t"
            "mbarrier.try_wait.parity.acquire.cta.shared::cta.b64 P1, [%0], %1, 0x989680;\n\t"
            "@P1 bra.uni WD_%=;\n\t"
            "bra.uni WL_%=;\n\t"
            "WD_%=:\n\t}"
            :: "r"(a), "r"(parity) : "memory");
    }
}
__device__ __forceinline__ void tma_load_2d(unsigned int smem_dst, const CUtensorMap* tm,
                                            int cx, int cy, unsigned int mbar) {
    asm volatile(
        "cp.async.bulk.tensor.2d.shared::cta.global.tile.mbarrier::complete_tx::bytes "
        "[%0], [%1, {%2, %3}], [%4];"
        :: "r"(smem_dst), "l"(tm), "r"(cx), "r"(cy), "r"(mbar) : "memory");
}

__device__ __forceinline__ void box_prologue(const float* boxes, int b, int tid, int lane, int wrp,
                                             BoxC* bc, unsigned int* sm_mask) {
    if (tid < NBOX) {
        const float* p = boxes + (b * NBOX + tid) * 7;
        const float p0 = p[0], p1 = p[1], p3 = p[3], p4 = p[4], p5 = p[5], p6 = p[6];
        BoxC v;
        v.cx = (p0 + 54.0f) * 5.0f;
        v.cy = (p1 + 54.0f) * 5.0f;
        v.hw = p3 * 2.5f;
        v.hl = p4 * 2.5f;
        float sn, cn;
        __sincosf(p6, &sn, &cn);
        v.c  = cn;
        v.s  = -sn;
        v.hv = p5 * 0.2f;
        bc[tid] = v;

        const float ex = fabsf(v.c) * v.hw + fabsf(v.s) * v.hl;
        const float ey = fabsf(v.s) * v.hw + fabsf(v.c) * v.hl;
        const float tx0 = (float)(blockIdx.x * TILE);
        const float ty0 = (float)(blockIdx.y * TILE);
        const bool hit = (v.cx - ex <= tx0 + (float)(TILE - 1)) && (v.cx + ex >= tx0) &&
                         (v.cy - ey <= ty0 + (float)(TILE - 1)) && (v.cy + ey >= ty0);
        const unsigned int m = __ballot_sync(0xffffffffu, hit);
        if (lane == 0) sm_mask[wrp] = m;
    }
}

__device__ __forceinline__ void raster4(unsigned int m0, unsigned int m1, const BoxC* bc,
                                        float fx0, float fy, float gt[4]) {
    #pragma unroll
    for (int half = 0; half < 2; half++) {
        unsigned int mm = half ? m1 : m0;
        const int base = half ? 32 : 0;
        while (mm) {
            const int i = __ffs(mm) - 1;
            mm &= mm - 1u;
            const BoxC v = bc[base + i];
            const float dx = fx0 - v.cx;
            const float dy = fy - v.cy;
            float lx = dx * v.c - dy * v.s;
            float ly = dx * v.s + dy * v.c;
            #pragma unroll
            for (int j = 0; j < 4; j++) {
                const bool inside = (fabsf(lx) <= v.hw) && (fabsf(ly) <= v.hl);
                gt[j] = inside ? v.hv : gt[j];
                lx += v.c;
                ly += v.s;
            }
        }
    }
}

template <bool CHECK>
__device__ __forceinline__ void loss4(bool ok, const float gt[4], const float* xvp, const float* hhp,
                                      float& sc0, float& sc1, int& cv) {
    #pragma unroll
    for (int j = 0; j < 4; j++) {
        const float g  = gt[j];
        const bool pos = (g > 0.0f);
        bool valid = pos || (hhp[j] > 0.0f);
        if (CHECK) valid = valid && ok;
        const float xl = xvp[j];

        const float weight = pos ? 5.0f : 0.1f;
        const float e  = __expf(-fabsf(xl));
        const float d  = 1.0f + e;
        const float bce = fmaxf(xl, 0.0f) - xl * g + __logf(d);
        const float rd = __fdividef(1.0f, d);
        const float p  = (xl >= 0.0f) ? rd : e * rd;
        const float u  = fmaf(p, 1.0f - 2.0f * g, g);
        const float aw = 0.75f - 0.5f * g;
        const float contrib = weight * bce * fmaf(u * u, aw, 1.0f);
        if (j & 1) sc1 += valid ? contrib : 0.0f;
        else       sc0 += valid ? contrib : 0.0f;
        cv += valid ? 1 : 0;
    }
}

// block-level finish (R13): smem stage + tid0 atomics — 1156 atomics total
__device__ __forceinline__ void finish_block(int b, int tid, int lane, int wrp,
                                             float sc, int cv,
                                             float* ws, int* wc, float* out) {
    const int cnt = __reduce_add_sync(0xffffffffu, cv);
    #pragma unroll
    for (int st = 16; st > 0; st >>= 1)
        sc += __shfl_xor_sync(0xffffffffu, sc, st);
    if (lane == 0) { ws[wrp] = sc; wc[wrp] = cnt; }
    __syncthreads();

    if (tid < 8) {
        float t1 = ws[tid];
        int   t0 = wc[tid];
        #pragma unroll
        for (int st = 4; st > 0; st >>= 1)
            t1 += __shfl_xor_sync(0x000000ffu, t1, st);
        t0 = __reduce_add_sync(0x000000ffu, t0);

        if (tid == 0) {
            atomicAdd(&g_acc[b][0], (unsigned long long)t0);
            atomicAdd(&g_acc[b][1], (unsigned long long)llrint((double)t1 * FIXSCALE));
            __threadfence();
            const unsigned int ticket = atomicAdd(&g_done, 1u);
            if (ticket == NBLOCKS - 1) {
                float total = 0.0f, ns = 0.0f;
                #pragma unroll
                for (int bb = 0; bb < BATCH; bb++) {
                    const double cnt_b = (double)g_acc[bb][0];
                    if (cnt_b > 0.0) {
                        const double s = (double)g_acc[bb][1] / FIXSCALE;
                        total += (float)(0.5 * s / fmax(cnt_b, 1.0));
                        ns += 1.0f;
                    }
                }
                out[0] = (ns > 0.0f) ? (total / fmaxf(ns, 1.0f)) : total;
                #pragma unroll
                for (int bb = 0; bb < BATCH; bb++) {
                    g_acc[bb][0] = 0ull; g_acc[bb][1] = 0ull;
                }
                __threadfence();
                g_done = 0u;
            }
        }
    }
}

// ---------------- TMA kernel ----------------
__global__ void __launch_bounds__(256)
hm_loss_tma_kernel(const __grid_constant__ CUtensorMap tml,
                   const __grid_constant__ CUtensorMap tmh,
                   const float* __restrict__ boxes,
                   float* __restrict__ out)
{
    __shared__ __align__(1024) float sL[TILE * TILE];
    __shared__ __align__(1024) float sH[TILE * TILE];
    __shared__ __align__(8) unsigned long long mbar;
    __shared__ BoxC bc[NBOX];
    __shared__ unsigned int sm_mask[2];
    __shared__ float ws[8];
    __shared__ int   wc[8];

    const int b    = blockIdx.z;
    const int tid  = threadIdx.x;
    const int lane = tid & 31;
    const int wrp  = tid >> 5;

    if (tid == 0) {
        const unsigned int mb = smem_u32(&mbar);
        mbar_init(mb, 1);
        asm volatile("fence.proxy.async.shared::cta;" ::: "memory");
        mbar_expect_tx(mb, 2 * TILE * TILE * 4);
        const int cx = blockIdx.x * TILE;
        const int cy = b * YS + blockIdx.y * TILE;
        tma_load_2d(smem_u32(sL), &tml, cx, cy, mb);
        tma_load_2d(smem_u32(sH), &tmh, cx, cy, mb);
    }

    box_prologue(boxes, b, tid, lane, wrp, bc, sm_mask);
    __syncthreads();

    const unsigned int m0 = sm_mask[0];
    const unsigned int m1 = sm_mask[1];

    const int x4 = blockIdx.x * TILE + (lane & 7) * 4;
    const int y  = blockIdx.y * TILE + (tid >> 3);

    float gt[4] = {0.f, 0.f, 0.f, 0.f};
    raster4(m0, m1, bc, (float)x4, (float)y, gt);

    mbar_wait(smem_u32(&mbar), 0);

    const int row = tid >> 3;
    unsigned int byte_off = (unsigned int)(row * 128 + (tid & 7) * 16);
    byte_off ^= ((byte_off >> 3) & 0x70u);   // SW128
    const float4 xl4 = *reinterpret_cast<const float4*>(
        reinterpret_cast<const char*>(sL) + byte_off);
    const float4 hh4 = *reinterpret_cast<const float4*>(
        reinterpret_cast<const char*>(sH) + byte_off);

    float sc0 = 0.0f, sc1 = 0.0f;
    int cv = 0;
    if (blockIdx.x < TXN - 1 && blockIdx.y < TYN - 1) {
        loss4<false>(true, gt, &xl4.x, &hh4.x, sc0, sc1, cv);
    } else {
        const bool ok = (x4 + 3 < XS) && (y < YS);
        loss4<true>(ok, gt, &xl4.x, &hh4.x, sc0, sc1, cv);
    }

    finish_block(b, tid, lane, wrp, sc0 + sc1, cv, ws, wc, out);
}

// ---------------- fallback LDG kernel ----------------
__global__ void __launch_bounds__(256)
hm_loss_ldg_kernel(const float* __restrict__ logits,
                   const float* __restrict__ boxes,
                   const float* __restrict__ hm,
                   float* __restrict__ out)
{
    __shared__ BoxC bc[NBOX];
    __shared__ unsigned int sm_mask[2];
    __shared__ float ws[8];
    __shared__ int   wc[8];

    const int b    = blockIdx.z;
    const int tid  = threadIdx.x;
    const int lane = tid & 31;
    const int wrp  = tid >> 5;

    const int x4 = blockIdx.x * TILE + (lane & 7) * 4;
    const int y  = blockIdx.y * TILE + (tid >> 3);
    const bool ok = (x4 + 3 < XS) && (y < YS);

    float4 xl4 = make_float4(0.f, 0.f, 0.f, 0.f);
    float4 hh4 = make_float4(0.f, 0.f, 0.f, 0.f);
    if (ok) {
        const int idx = (b * YS + y) * XS + x4;
        xl4 = *reinterpret_cast<const float4*>(logits + idx);
        hh4 = *reinterpret_cast<const float4*>(hm + idx);
    }

    box_prologue(boxes, b, tid, lane, wrp, bc, sm_mask);
    __syncthreads();

    float gt[4] = {0.f, 0.f, 0.f, 0.f};
    raster4(sm_mask[0], sm_mask[1], bc, (float)x4, (float)y, gt);

    float sc0 = 0.0f, sc1 = 0.0f;
    int cv = 0;
    loss4<true>(ok, gt, &xl4.x, &hh4.x, sc0, sc1, cv);

    finish_block(b, tid, lane, wrp, sc0 + sc1, cv, ws, wc, out);
}

// ---------------- host ----------------
typedef CUresult (*EncFn)(CUtensorMap*, CUtensorMapDataType, cuuint32_t, void*,
                          const cuuint64_t*, const cuuint64_t*, const cuuint32_t*,
                          const cuuint32_t*, CUtensorMapInterleave, CUtensorMapSwizzle,
                          CUtensorMapL2promotion, CUtensorMapFloatOOBfill);

static EncFn get_encoder() {
    static EncFn fn = nullptr;
    static bool tried = false;
    if (!tried) {
        tried = true;
        void* p = nullptr;
        cudaDriverEntryPointQueryResult qr;
        if (cudaGetDriverEntryPointByVersion("cuTensorMapEncodeTiled", &p, 12000,
                                             cudaEnableDefault, &qr) == cudaSuccess &&
            qr == cudaDriverEntryPointSuccess) {
            fn = (EncFn)p;
        }
    }
    return fn;
}

static bool make_tmap(CUtensorMap* tm, const float* base, EncFn enc) {
    cuuint64_t gdim[2]    = { (cuuint64_t)XS, (cuuint64_t)(BATCH * YS) };
    cuuint64_t gstride[1] = { (cuuint64_t)XS * sizeof(float) };
    cuuint32_t box[2]     = { TILE, TILE };
    cuuint32_t estr[2]    = { 1, 1 };
    CUresult r = enc(tm, CU_TENSOR_MAP_DATA_TYPE_FLOAT32, 2, (void*)base,
                     gdim, gstride, box, estr,
                     CU_TENSOR_MAP_INTERLEAVE_NONE, CU_TENSOR_MAP_SWIZZLE_128B,
                     CU_TENSOR_MAP_L2_PROMOTION_L2_128B,
                     CU_TENSOR_MAP_FLOAT_OOB_FILL_NONE);
    return r == CUDA_SUCCESS;
}

extern "C" void kernel_launch(void* const* d_in, const int* in_sizes, int n_in,
                              void* d_out, int out_size)
{
    const float* arrs[3] = { (const float*)d_in[0],
                             (const float*)d_in[1],
                             (const float*)d_in[2] };
    const float* logits = arrs[0];
    const float* boxes  = arrs[1];
    const float* hmap   = arrs[2];
    if (n_in >= 3) {
        int bi = -1;
        for (int i = 0; i < 3; i++)
            if (in_sizes[i] == BATCH * NBOX * 7) { bi = i; break; }
        if (bi >= 0) {
            boxes = arrs[bi];
            int o0 = -1, o1 = -1;
            for (int i = 0; i < 3; i++) {
                if (i == bi) continue;
                if (o0 < 0) o0 = i; else o1 = i;
            }
            logits = arrs[o0];
            hmap   = arrs[o1];
        }
    }

    dim3 block(256, 1, 1);
    dim3 grid(TXN, TYN, BATCH);

    EncFn enc = get_encoder();
    CUtensorMap tml, tmh;
    bool tma_ok = false;
    if (enc) {
        tma_ok = make_tmap(&tml, logits, enc) && make_tmap(&tmh, hmap, enc);
    }

    if (tma_ok) {
        hm_loss_tma_kernel<<<grid, block>>>(tml, tmh, boxes, (float*)d_out);
    } else {
        hm_loss_ldg_kernel<<<grid, block>>>(logits, boxes, hmap, (float*)d_out);
    }
}

// round 16
// speedup vs baseline: 2.3672x; 1.1910x over previous
#include <cuda_runtime.h>
#include <cuda.h>
#include <math.h>

#define XS 540
#define YS 540
#define BATCH 4
#define NBOX 64
#define TILE 32
#define TXN 17
#define TYN 17
#define NBLOCKS (TXN*TYN*BATCH)
#define FIXSCALE 67108864.0   // 2^26

__device__ unsigned long long g_acc[BATCH][2];
__device__ unsigned int g_done;

struct BoxC { float cx, cy, c, s, hw, hl, hv; };

// ---------------- device helpers ----------------
__device__ __forceinline__ unsigned int smem_u32(const void* p) {
    return (unsigned int)__cvta_generic_to_shared(p);
}
__device__ __forceinline__ void mbar_init(unsigned int a, unsigned int cnt) {
    asm volatile("mbarrier.init.shared.b64 [%0], %1;" :: "r"(a), "r"(cnt) : "memory");
}
__device__ __forceinline__ void mbar_expect_tx(unsigned int a, unsigned int bytes) {
    asm volatile("mbarrier.arrive.expect_tx.shared.b64 _, [%0], %1;" :: "r"(a), "r"(bytes) : "memory");
}
__device__ __forceinline__ void mbar_wait(unsigned int a, unsigned int parity) {
    unsigned int done;
    asm volatile(
        "{\n\t.reg .pred p;\n\t"
        "mbarrier.try_wait.parity.acquire.cta.shared::cta.b64 p, [%1], %2;\n\t"
        "selp.b32 %0, 1, 0, p;\n\t}"
        : "=r"(done) : "r"(a), "r"(parity) : "memory");
    if (!done) {
        asm volatile(
            "{\n\t.reg .pred P1;\n\t"
            "WL_%=:\n\t"
            "mbarrier.try_wait.parity.acquire.cta.shared::cta.b64 P1, [%0], %1, 0x989680;\n\t"
            "@P1 bra.uni WD_%=;\n\t"
            "bra.uni WL_%=;\n\t"
            "WD_%=:\n\t}"
            :: "r"(a), "r"(parity) : "memory");
    }
}
__device__ __forceinline__ void tma_load_2d(unsigned int smem_dst, const CUtensorMap* tm,
                                            int cx, int cy, unsigned int mbar) {
    asm volatile(
        "cp.async.bulk.tensor.2d.shared::cta.global.tile.mbarrier::complete_tx::bytes "
        "[%0], [%1, {%2, %3}], [%4];"
        :: "r"(smem_dst), "l"(tm), "r"(cx), "r"(cy), "r"(mbar) : "memory");
}

__device__ __forceinline__ void box_prologue(const float* boxes, int b, int tid, int lane, int wrp,
                                             BoxC* bc, unsigned int* sm_mask) {
    if (tid < NBOX) {
        const float* p = boxes + (b * NBOX + tid) * 7;
        const float p0 = p[0], p1 = p[1], p3 = p[3], p4 = p[4], p5 = p[5], p6 = p[6];
        BoxC v;
        v.cx = (p0 + 54.0f) * 5.0f;
        v.cy = (p1 + 54.0f) * 5.0f;
        v.hw = p3 * 2.5f;
        v.hl = p4 * 2.5f;
        float sn, cn;
        __sincosf(p6, &sn, &cn);
        v.c  = cn;
        v.s  = -sn;
        v.hv = p5 * 0.2f;
        bc[tid] = v;

        const float ex = fabsf(v.c) * v.hw + fabsf(v.s) * v.hl;
        const float ey = fabsf(v.s) * v.hw + fabsf(v.c) * v.hl;
        const float tx0 = (float)(blockIdx.x * TILE);
        const float ty0 = (float)(blockIdx.y * TILE);
        const bool hit = (v.cx - ex <= tx0 + (float)(TILE - 1)) && (v.cx + ex >= tx0) &&
                         (v.cy - ey <= ty0 + (float)(TILE - 1)) && (v.cy + ey >= ty0);
        const unsigned int m = __ballot_sync(0xffffffffu, hit);
        if (lane == 0) sm_mask[wrp] = m;
    }
}

__device__ __forceinline__ void raster4(unsigned int m0, unsigned int m1, const BoxC* bc,
                                        float fx0, float fy, float gt[4]) {
    #pragma unroll
    for (int half = 0; half < 2; half++) {
        unsigned int mm = half ? m1 : m0;
        const int base = half ? 32 : 0;
        while (mm) {
            const int i = __ffs(mm) - 1;
            mm &= mm - 1u;
            const BoxC v = bc[base + i];
            const float dx = fx0 - v.cx;
            const float dy = fy - v.cy;
            float lx = dx * v.c - dy * v.s;
            float ly = dx * v.s + dy * v.c;
            #pragma unroll
            for (int j = 0; j < 4; j++) {
                const bool inside = (fabsf(lx) <= v.hw) && (fabsf(ly) <= v.hl);
                gt[j] = inside ? v.hv : gt[j];
                lx += v.c;
                ly += v.s;
            }
        }
    }
}

__device__ __forceinline__ void loss4(bool ok, const float gt[4], const float* xvp, const float* hhp,
                                      float& sc0, float& sc1, int& cv) {
    #pragma unroll
    for (int j = 0; j < 4; j++) {
        const float g  = gt[j];
        const bool pos = (g > 0.0f);
        const bool valid = ok && (pos || (hhp[j] > 0.0f));
        const float xl = xvp[j];

        const float weight = pos ? 5.0f : 0.1f;
        const float e  = __expf(-fabsf(xl));
        const float d  = 1.0f + e;
        const float bce = fmaxf(xl, 0.0f) - xl * g + __logf(d);
        const float rd = __fdividef(1.0f, d);
        const float p  = (xl >= 0.0f) ? rd : e * rd;
        const float u  = fmaf(p, 1.0f - 2.0f * g, g);
        const float aw = 0.75f - 0.5f * g;
        const float contrib = weight * bce * fmaf(u * u, aw, 1.0f);
        if (j & 1) sc1 += valid ? contrib : 0.0f;
        else       sc0 += valid ? contrib : 0.0f;
        cv += valid ? 1 : 0;
    }
}

// block-level finish; final-block finalize is warp-parallel (lanes 0-3, one batch each)
__device__ __forceinline__ void finish_block(int b, int tid, int lane, int wrp,
                                             float sc, int cv,
                                             float* ws, int* wc, float* out) {
    const int cnt = __reduce_add_sync(0xffffffffu, cv);
    #pragma unroll
    for (int st = 16; st > 0; st >>= 1)
        sc += __shfl_xor_sync(0xffffffffu, sc, st);
    if (lane == 0) { ws[wrp] = sc; wc[wrp] = cnt; }
    __syncthreads();

    if (tid < 8) {
        float t1 = ws[tid];
        int   t0 = wc[tid];
        #pragma unroll
        for (int st = 4; st > 0; st >>= 1)
            t1 += __shfl_xor_sync(0x000000ffu, t1, st);
        t0 = __reduce_add_sync(0x000000ffu, t0);

        unsigned int ticket = 0xffffffffu;
        if (tid == 0) {
            atomicAdd(&g_acc[b][0], (unsigned long long)t0);
            atomicAdd(&g_acc[b][1], (unsigned long long)llrint((double)t1 * FIXSCALE));
            __threadfence();
            ticket = atomicAdd(&g_done, 1u);
        }
        ticket = __shfl_sync(0x000000ffu, ticket, 0);

        if (ticket == NBLOCKS - 1) {
            // warp-parallel finalize: lane bb (0..3) handles batch bb
            float term = 0.0f, has = 0.0f;
            if (tid < BATCH) {
                const unsigned long long c0 = g_acc[tid][0];   // independent LDGs across lanes
                const unsigned long long s0 = g_acc[tid][1];
                if (c0 > 0ull) {
                    const double s = (double)s0 / FIXSCALE;
                    term = (float)(0.5 * s / fmax((double)c0, 1.0));
                    has = 1.0f;
                }
                g_acc[tid][0] = 0ull;
                g_acc[tid][1] = 0ull;
            }
            #pragma unroll
            for (int st = 2; st > 0; st >>= 1) {
                term += __shfl_xor_sync(0x000000ffu, term, st);
                has  += __shfl_xor_sync(0x000000ffu, has,  st);
            }
            if (tid == 0) {
                out[0] = (has > 0.0f) ? (term / fmaxf(has, 1.0f)) : term;
                g_done = 0u;   // kernel boundary orders this for the next replay
            }
        }
    }
}

// ---------------- TMA kernel ----------------
__global__ void __launch_bounds__(256)
hm_loss_tma_kernel(const __grid_constant__ CUtensorMap tml,
                   const __grid_constant__ CUtensorMap tmh,
                   const float* __restrict__ boxes,
                   float* __restrict__ out)
{
    __shared__ __align__(1024) float sL[TILE * TILE];
    __shared__ __align__(1024) float sH[TILE * TILE];
    __shared__ __align__(8) unsigned long long mbar;
    __shared__ BoxC bc[NBOX];
    __shared__ unsigned int sm_mask[2];
    __shared__ float ws[8];
    __shared__ int   wc[8];

    const int b    = blockIdx.z;
    const int tid  = threadIdx.x;
    const int lane = tid & 31;
    const int wrp  = tid >> 5;

    if (tid == 0) {
        const unsigned int mb = smem_u32(&mbar);
        mbar_init(mb, 1);
        asm volatile("fence.proxy.async.shared::cta;" ::: "memory");
        mbar_expect_tx(mb, 2 * TILE * TILE * 4);
        const int cx = blockIdx.x * TILE;
        const int cy = b * YS + blockIdx.y * TILE;
        tma_load_2d(smem_u32(sL), &tml, cx, cy, mb);
        tma_load_2d(smem_u32(sH), &tmh, cx, cy, mb);
    }

    box_prologue(boxes, b, tid, lane, wrp, bc, sm_mask);
    __syncthreads();

    const unsigned int m0 = sm_mask[0];
    const unsigned int m1 = sm_mask[1];

    const int x4 = blockIdx.x * TILE + (lane & 7) * 4;
    const int y  = blockIdx.y * TILE + (tid >> 3);
    const bool ok = (x4 + 3 < XS) && (y < YS);

    float gt[4] = {0.f, 0.f, 0.f, 0.f};
    raster4(m0, m1, bc, (float)x4, (float)y, gt);

    mbar_wait(smem_u32(&mbar), 0);

    const int row = tid >> 3;
    unsigned int byte_off = (unsigned int)(row * 128 + (tid & 7) * 16);
    byte_off ^= ((byte_off >> 3) & 0x70u);   // SW128
    const float4 xl4 = *reinterpret_cast<const float4*>(
        reinterpret_cast<const char*>(sL) + byte_off);
    const float4 hh4 = *reinterpret_cast<const float4*>(
        reinterpret_cast<const char*>(sH) + byte_off);

    float sc0 = 0.0f, sc1 = 0.0f;
    int cv = 0;
    loss4(ok, gt, &xl4.x, &hh4.x, sc0, sc1, cv);

    finish_block(b, tid, lane, wrp, sc0 + sc1, cv, ws, wc, out);
}

// ---------------- fallback LDG kernel ----------------
__global__ void __launch_bounds__(256)
hm_loss_ldg_kernel(const float* __restrict__ logits,
                   const float* __restrict__ boxes,
                   const float* __restrict__ hm,
                   float* __restrict__ out)
{
    __shared__ BoxC bc[NBOX];
    __shared__ unsigned int sm_mask[2];
    __shared__ float ws[8];
    __shared__ int   wc[8];

    const int b    = blockIdx.z;
    const int tid  = threadIdx.x;
    const int lane = tid & 31;
    const int wrp  = tid >> 5;

    const int x4 = blockIdx.x * TILE + (lane & 7) * 4;
    const int y  = blockIdx.y * TILE + (tid >> 3);
    const bool ok = (x4 + 3 < XS) && (y < YS);

    float4 xl4 = make_float4(0.f, 0.f, 0.f, 0.f);
    float4 hh4 = make_float4(0.f, 0.f, 0.f, 0.f);
    if (ok) {
        const int idx = (b * YS + y) * XS + x4;
        xl4 = *reinterpret_cast<const float4*>(logits + idx);
        hh4 = *reinterpret_cast<const float4*>(hm + idx);
    }

    box_prologue(boxes, b, tid, lane, wrp, bc, sm_mask);
    __syncthreads();

    float gt[4] = {0.f, 0.f, 0.f, 0.f};
    raster4(sm_mask[0], sm_mask[1], bc, (float)x4, (float)y, gt);

    float sc0 = 0.0f, sc1 = 0.0f;
    int cv = 0;
    loss4(ok, gt, &xl4.x, &hh4.x, sc0, sc1, cv);

    finish_block(b, tid, lane, wrp, sc0 + sc1, cv, ws, wc, out);
}

// ---------------- host ----------------
typedef CUresult (*EncFn)(CUtensorMap*, CUtensorMapDataType, cuuint32_t, void*,
                          const cuuint64_t*, const cuuint64_t*, const cuuint32_t*,
                          const cuuint32_t*, CUtensorMapInterleave, CUtensorMapSwizzle,
                          CUtensorMapL2promotion, CUtensorMapFloatOOBfill);

static EncFn get_encoder() {
    static EncFn fn = nullptr;
    static bool tried = false;
    if (!tried) {
        tried = true;
        void* p = nullptr;
        cudaDriverEntryPointQueryResult qr;
        if (cudaGetDriverEntryPointByVersion("cuTensorMapEncodeTiled", &p, 12000,
                                             cudaEnableDefault, &qr) == cudaSuccess &&
            qr == cudaDriverEntryPointSuccess) {
            fn = (EncFn)p;
        }
    }
    return fn;
}

static bool make_tmap(CUtensorMap* tm, const float* base, EncFn enc) {
    cuuint64_t gdim[2]    = { (cuuint64_t)XS, (cuuint64_t)(BATCH * YS) };
    cuuint64_t gstride[1] = { (cuuint64_t)XS * sizeof(float) };
    cuuint32_t box[2]     = { TILE, TILE };
    cuuint32_t estr[2]    = { 1, 1 };
    CUresult r = enc(tm, CU_TENSOR_MAP_DATA_TYPE_FLOAT32, 2, (void*)base,
                     gdim, gstride, box, estr,
                     CU_TENSOR_MAP_INTERLEAVE_NONE, CU_TENSOR_MAP_SWIZZLE_128B,
                     CU_TENSOR_MAP_L2_PROMOTION_L2_128B,
                     CU_TENSOR_MAP_FLOAT_OOB_FILL_NONE);
    return r == CUDA_SUCCESS;
}

extern "C" void kernel_launch(void* const* d_in, const int* in_sizes, int n_in,
                              void* d_out, int out_size)
{
    const float* arrs[3] = { (const float*)d_in[0],
                             (const float*)d_in[1],
                             (const float*)d_in[2] };
    const float* logits = arrs[0];
    const float* boxes  = arrs[1];
    const float* hmap   = arrs[2];
    if (n_in >= 3) {
        int bi = -1;
        for (int i = 0; i < 3; i++)
            if (in_sizes[i] == BATCH * NBOX * 7) { bi = i; break; }
        if (bi >= 0) {
            boxes = arrs[bi];
            int o0 = -1, o1 = -1;
            for (int i = 0; i < 3; i++) {
                if (i == bi) continue;
                if (o0 < 0) o0 = i; else o1 = i;
            }
            logits = arrs[o0];
            hmap   = arrs[o1];
        }
    }

    dim3 block(256, 1, 1);
    dim3 grid(TXN, TYN, BATCH);

    EncFn enc = get_encoder();
    CUtensorMap tml, tmh;
    bool tma_ok = false;
    if (enc) {
        tma_ok = make_tmap(&tml, logits, enc) && make_tmap(&tmh, hmap, enc);
    }

    if (tma_ok) {
        hm_loss_tma_kernel<<<grid, block>>>(tml, tmh, boxes, (float*)d_out);
    } else {
        hm_loss_ldg_kernel<<<grid, block>>>(logits, boxes, hmap, (float*)d_out);
    }
}